// round 3
// baseline (speedup 1.0000x reference)
#include <cuda_runtime.h>

#define NT0 7
#define NT1 24
#define NT2 288
#define NTP 2048
#define DM  512
#define BB  32
#define PP  2048

// raw (per-K-half) table layout, rows: T0[7] T1[24] T2[288] Tp[2048]
#define RT0 0
#define RT1 (NT0*DM)
#define RT2 ((NT0+NT1)*DM)
#define RTP ((NT0+NT1+NT2)*DM)
#define RAW_FLOATS ((NT0+NT1+NT2+NTP)*DM)

// final tables: T01[168] T2[288] Tp[2048]
#define OT01 0
#define OT2  (168*DM)
#define OTP  ((168+NT2)*DM)
#define TAB_FLOATS ((168+NT2+NTP)*DM)

__device__ __align__(16) float g_rawA[RAW_FLOATS];
__device__ __align__(16) float g_rawB[RAW_FLOATS];
__device__ __align__(16) float g_tab[TAB_FLOATS];

// ---------------- f32x2 helpers ----------------
__device__ __forceinline__ void fma2(unsigned long long& d, unsigned long long a, unsigned long long b) {
    asm("fma.rn.f32x2 %0, %1, %2, %3;" : "=l"(d) : "l"(a), "l"(b), "l"(d));
}
__device__ __forceinline__ float2 unpack2(unsigned long long v) {
    float2 r;
    asm("mov.b64 {%0, %1}, %2;" : "=f"(r.x), "=f"(r.y) : "l"(v));
    return r;
}

// ---------------------------------------------------------------------------
// Kernel 1: table GEMM, FFMA2, split-K=2.
// Tile 64 rows x 32 cols, 64 threads, micro 8x4 row-paired f32x2.
// grid = (39 row-tiles, 16 col-tiles, 2 K-halves) = 1248 blocks.
// B stored in smem PRE-DUPLICATED (float2 dup per col) so inner loop has no packs.
// ---------------------------------------------------------------------------
__global__ __launch_bounds__(64) void table_gemm_kernel(
        const float* __restrict__ emb0, const float* __restrict__ emb1,
        const float* __restrict__ emb2, const float* __restrict__ pe,
        const float* __restrict__ W) {
    __shared__ __align__(16) float  As[2][16][64];       // [k][row]
    __shared__ __align__(16) float2 Bs[2][16][32];       // [k][col] dup pairs

    const int bt = blockIdx.x;
    const float* src;
    float* dst;
    int M, rowBase, wRow;
    if (bt == 0)      { src = emb0; M = NT0; rowBase = 0;         wRow = 0;    dst = 0; }
    else if (bt == 1) { src = emb1; M = NT1; rowBase = 0;         wRow = DM;   dst = 0; }
    else if (bt < 7)  { src = emb2; M = NT2; rowBase = (bt-2)*64; wRow = 2*DM; dst = 0; }
    else              { src = pe;   M = NTP; rowBase = (bt-7)*64; wRow = 3*DM; dst = 0; }
    float* raw = blockIdx.z ? g_rawB : g_rawA;
    if (bt == 0)      dst = raw + RT0;
    else if (bt == 1) dst = raw + RT1;
    else if (bt < 7)  dst = raw + RT2;
    else              dst = raw + RTP;

    const int kOff = blockIdx.z * 256;     // this block's K half

    const int tid = threadIdx.x;            // 0..63
    const int ty8 = (tid >> 3) * 8;         // row offset 0..56
    const int tx4 = (tid & 7) * 4;          // col offset 0..28
    const int colBase = blockIdx.y * 32;

    const int arow = rowBase + tid;
    const bool aok = (arow < M);
    const float* aptr = src + (size_t)arow * DM + kOff;

    // B load indices (2 float4 of W per thread per chunk)
    const int kb0 = tid >> 3,        cb0 = (tid & 7) * 4;
    const int kb1 = (64 + tid) >> 3, cb1 = cb0;
    const float* wbase = W + (size_t)(wRow + kOff) * DM + colBase;

    unsigned long long acc[4][4];
    #pragma unroll
    for (int i = 0; i < 4; i++)
        #pragma unroll
        for (int c = 0; c < 4; c++) acc[i][c] = 0ull;

    float4 pa[4], pb0, pb1;

    // prefetch + store chunk 0
    #pragma unroll
    for (int j = 0; j < 4; j++)
        pa[j] = aok ? *reinterpret_cast<const float4*>(aptr + 4*j)
                    : make_float4(0.f,0.f,0.f,0.f);
    pb0 = *reinterpret_cast<const float4*>(wbase + (size_t)kb0 * DM + cb0);
    pb1 = *reinterpret_cast<const float4*>(wbase + (size_t)kb1 * DM + cb1);

    #pragma unroll
    for (int j = 0; j < 4; j++) {
        As[0][4*j+0][tid] = pa[j].x; As[0][4*j+1][tid] = pa[j].y;
        As[0][4*j+2][tid] = pa[j].z; As[0][4*j+3][tid] = pa[j].w;
    }
    Bs[0][kb0][cb0+0] = make_float2(pb0.x, pb0.x);
    Bs[0][kb0][cb0+1] = make_float2(pb0.y, pb0.y);
    Bs[0][kb0][cb0+2] = make_float2(pb0.z, pb0.z);
    Bs[0][kb0][cb0+3] = make_float2(pb0.w, pb0.w);
    Bs[0][kb1][cb1+0] = make_float2(pb1.x, pb1.x);
    Bs[0][kb1][cb1+1] = make_float2(pb1.y, pb1.y);
    Bs[0][kb1][cb1+2] = make_float2(pb1.z, pb1.z);
    Bs[0][kb1][cb1+3] = make_float2(pb1.w, pb1.w);
    __syncthreads();

    #pragma unroll 1
    for (int ch = 0; ch < 16; ch++) {
        const int buf = ch & 1;
        if (ch < 15) {
            const int k0 = (ch + 1) * 16;
            #pragma unroll
            for (int j = 0; j < 4; j++)
                pa[j] = aok ? *reinterpret_cast<const float4*>(aptr + k0 + 4*j)
                            : make_float4(0.f,0.f,0.f,0.f);
            pb0 = *reinterpret_cast<const float4*>(wbase + (size_t)(k0 + kb0) * DM + cb0);
            pb1 = *reinterpret_cast<const float4*>(wbase + (size_t)(k0 + kb1) * DM + cb1);
        }

        #pragma unroll
        for (int kk = 0; kk < 16; kk++) {
            ulonglong2 aA = *reinterpret_cast<const ulonglong2*>(&As[buf][kk][ty8]);
            ulonglong2 aB = *reinterpret_cast<const ulonglong2*>(&As[buf][kk][ty8 + 4]);
            ulonglong2 b01 = *reinterpret_cast<const ulonglong2*>(&Bs[buf][kk][tx4]);
            ulonglong2 b23 = *reinterpret_cast<const ulonglong2*>(&Bs[buf][kk][tx4 + 2]);
            unsigned long long a2[4] = {aA.x, aA.y, aB.x, aB.y};
            #pragma unroll
            for (int i = 0; i < 4; i++) {
                fma2(acc[i][0], a2[i], b01.x);
                fma2(acc[i][1], a2[i], b01.y);
                fma2(acc[i][2], a2[i], b23.x);
                fma2(acc[i][3], a2[i], b23.y);
            }
        }

        if (ch < 15) {
            const int nb = buf ^ 1;
            #pragma unroll
            for (int j = 0; j < 4; j++) {
                As[nb][4*j+0][tid] = pa[j].x; As[nb][4*j+1][tid] = pa[j].y;
                As[nb][4*j+2][tid] = pa[j].z; As[nb][4*j+3][tid] = pa[j].w;
            }
            Bs[nb][kb0][cb0+0] = make_float2(pb0.x, pb0.x);
            Bs[nb][kb0][cb0+1] = make_float2(pb0.y, pb0.y);
            Bs[nb][kb0][cb0+2] = make_float2(pb0.z, pb0.z);
            Bs[nb][kb0][cb0+3] = make_float2(pb0.w, pb0.w);
            Bs[nb][kb1][cb1+0] = make_float2(pb1.x, pb1.x);
            Bs[nb][kb1][cb1+1] = make_float2(pb1.y, pb1.y);
            Bs[nb][kb1][cb1+2] = make_float2(pb1.z, pb1.z);
            Bs[nb][kb1][cb1+3] = make_float2(pb1.w, pb1.w);
            __syncthreads();
        }
    }

    #pragma unroll
    for (int i = 0; i < 4; i++) {
        float2 u0 = unpack2(acc[i][0]);
        float2 u1 = unpack2(acc[i][1]);
        float2 u2 = unpack2(acc[i][2]);
        float2 u3 = unpack2(acc[i][3]);
        int re = rowBase + ty8 + 2*i;
        if (re < M) {
            float4 o = make_float4(u0.x, u1.x, u2.x, u3.x);
            *reinterpret_cast<float4*>(dst + (size_t)re * DM + colBase + tx4) = o;
        }
        if (re + 1 < M) {
            float4 o = make_float4(u0.y, u1.y, u2.y, u3.y);
            *reinterpret_cast<float4*>(dst + (size_t)(re + 1) * DM + colBase + tx4) = o;
        }
    }
}

// ---------------------------------------------------------------------------
// Kernel 2: reduce K-halves + fuse T01 = T0[i]+T1[j] + add bias to Tp.
// grid = 168 + 288 + 2048 = 2504 rows, 128 threads (float4 each).
// ---------------------------------------------------------------------------
__global__ void reduce_kernel(const float* __restrict__ bias) {
    const int r = blockIdx.x;
    const int c = 4 * threadIdx.x;

    float4 o;
    float* dst;
    if (r < 168) {
        const int i = r / 24, j = r % 24;
        float4 a0 = *reinterpret_cast<const float4*>(g_rawA + RT0 + (size_t)i * DM + c);
        float4 b0 = *reinterpret_cast<const float4*>(g_rawB + RT0 + (size_t)i * DM + c);
        float4 a1 = *reinterpret_cast<const float4*>(g_rawA + RT1 + (size_t)j * DM + c);
        float4 b1 = *reinterpret_cast<const float4*>(g_rawB + RT1 + (size_t)j * DM + c);
        o = make_float4(a0.x + b0.x + a1.x + b1.x,
                        a0.y + b0.y + a1.y + b1.y,
                        a0.z + b0.z + a1.z + b1.z,
                        a0.w + b0.w + a1.w + b1.w);
        dst = g_tab + OT01 + (size_t)r * DM + c;
    } else if (r < 168 + NT2) {
        const int rr = r - 168;
        float4 a = *reinterpret_cast<const float4*>(g_rawA + RT2 + (size_t)rr * DM + c);
        float4 b = *reinterpret_cast<const float4*>(g_rawB + RT2 + (size_t)rr * DM + c);
        o = make_float4(a.x + b.x, a.y + b.y, a.z + b.z, a.w + b.w);
        dst = g_tab + OT2 + (size_t)rr * DM + c;
    } else {
        const int rr = r - 168 - NT2;
        float4 a = *reinterpret_cast<const float4*>(g_rawA + RTP + (size_t)rr * DM + c);
        float4 b = *reinterpret_cast<const float4*>(g_rawB + RTP + (size_t)rr * DM + c);
        float4 bb = *reinterpret_cast<const float4*>(bias + c);
        o = make_float4(a.x + b.x + bb.x, a.y + b.y + bb.y,
                        a.z + b.z + bb.z, a.w + b.w + bb.w);
        dst = g_tab + OTP + (size_t)rr * DM + c;
    }
    *reinterpret_cast<float4*>(dst) = o;
}

// ---------------------------------------------------------------------------
// Kernel 3: gather-add. 256 threads = 2 positions/block, grid 1024.
// out[token] = T01[i0*24+i1] + T2[i2] + Tp[l]
// ---------------------------------------------------------------------------
__global__ void gather_kernel(const int* __restrict__ in0, const int* __restrict__ tg0,
                              const int* __restrict__ in1, const int* __restrict__ tg1,
                              const int* __restrict__ in2, const int* __restrict__ tg2,
                              float* __restrict__ out) {
    const int t = threadIdx.x;
    const int half = t >> 7;           // which position
    const int lane = t & 127;          // column group
    const int l = blockIdx.x * 2 + half;

    __shared__ int s01[2][64], s2[2][64];
    if (lane < 64) {
        int s = lane >> 5, b = lane & 31;
        int off = b * PP + l;
        int i0 = (s ? tg0 : in0)[off];
        int i1 = (s ? tg1 : in1)[off];
        int i2 = (s ? tg2 : in2)[off];
        s01[half][lane] = i0 * 24 + i1;
        s2[half][lane]  = i2;
    }

    const float4 tp = *reinterpret_cast<const float4*>(g_tab + OTP + (size_t)l * DM + 4 * lane);

    __syncthreads();

    float4* outv = reinterpret_cast<float4*>(out);

    #pragma unroll 4
    for (int p = 0; p < 64; p++) {
        const float4 v01 = *reinterpret_cast<const float4*>(g_tab + OT01 + (size_t)s01[half][p] * DM + 4 * lane);
        const float4 v2  = *reinterpret_cast<const float4*>(g_tab + OT2  + (size_t)s2[half][p]  * DM + 4 * lane);
        float4 o;
        o.x = v01.x + v2.x + tp.x;
        o.y = v01.y + v2.y + tp.y;
        o.z = v01.z + v2.z + tp.z;
        o.w = v01.w + v2.w + tp.w;
        outv[((size_t)p * PP + l) * (DM / 4) + lane] = o;
    }
}

extern "C" void kernel_launch(void* const* d_in, const int* in_sizes, int n_in,
                              void* d_out, int out_size) {
    const int*   in0  = (const int*)d_in[0];
    const int*   tg0  = (const int*)d_in[1];
    const int*   in1  = (const int*)d_in[2];
    const int*   tg1  = (const int*)d_in[3];
    const int*   in2  = (const int*)d_in[4];
    const int*   tg2  = (const int*)d_in[5];
    const float* emb0 = (const float*)d_in[6];
    const float* emb1 = (const float*)d_in[7];
    const float* emb2 = (const float*)d_in[8];
    const float* pe   = (const float*)d_in[9];
    const float* W    = (const float*)d_in[10];
    const float* bias = (const float*)d_in[11];
    float* out = (float*)d_out;

    dim3 ggrid(39, 16, 2);
    table_gemm_kernel<<<ggrid, 64>>>(emb0, emb1, emb2, pe, W);
    reduce_kernel<<<2504, 128>>>(bias);
    gather_kernel<<<1024, 256>>>(in0, tg0, in1, tg1, in2, tg2, out);
}

// round 4
// speedup vs baseline: 1.0619x; 1.0619x over previous
#include <cuda_runtime.h>

#define NT0 7
#define NT1 24
#define NT2 288
#define NTP 2048
#define DM  512
#define BB  32
#define PP  2048

// raw (per-K-half) table layout, rows: T0[7] T1[24] T2[288] Tp[2048]
#define RT0 0
#define RT1 (NT0*DM)
#define RT2 ((NT0+NT1)*DM)
#define RTP ((NT0+NT1+NT2)*DM)
#define RAW_FLOATS ((NT0+NT1+NT2+NTP)*DM)

// final tables: T01[168] T2[288] Tp[2048]
#define OT01 0
#define OT2  (168*DM)
#define OTP  ((168+NT2)*DM)
#define TAB_FLOATS ((168+NT2+NTP)*DM)

__device__ __align__(16) float g_rawA[RAW_FLOATS];
__device__ __align__(16) float g_rawB[RAW_FLOATS];
__device__ __align__(16) float g_tab[TAB_FLOATS];

// ---------------- f32x2 helpers ----------------
__device__ __forceinline__ void fma2(unsigned long long& d, unsigned long long a, unsigned long long b) {
    asm("fma.rn.f32x2 %0, %1, %2, %3;" : "=l"(d) : "l"(a), "l"(b), "l"(d));
}
__device__ __forceinline__ float2 unpack2(unsigned long long v) {
    float2 r;
    asm("mov.b64 {%0, %1}, %2;" : "=f"(r.x), "=f"(r.y) : "l"(v));
    return r;
}

// ---------------------------------------------------------------------------
// Kernel 1: table GEMM, FFMA2, split-K=2, 128 THREADS (4 warps -> all SMSPs).
// Tile 64 rows x 64 cols; thread micro-tile 8 rows x 4 cols (f32x2 row pairs).
// grid = (39 row-tiles, 8 col-tiles, 2 K-halves) = 624 blocks.
// B stored in smem pre-duplicated (float2 dup per col): no packs in inner loop.
// ---------------------------------------------------------------------------
__global__ __launch_bounds__(128) void table_gemm_kernel(
        const float* __restrict__ emb0, const float* __restrict__ emb1,
        const float* __restrict__ emb2, const float* __restrict__ pe,
        const float* __restrict__ W) {
    __shared__ __align__(16) float  As[2][16][64];   // [k][row]
    __shared__ __align__(16) float2 Bs[2][16][64];   // [k][col] dup pairs

    const int bt = blockIdx.x;
    const float* src;
    int M, rowBase, wRow, tabOff;
    if (bt == 0)      { src = emb0; M = NT0; rowBase = 0;         wRow = 0;    tabOff = RT0; }
    else if (bt == 1) { src = emb1; M = NT1; rowBase = 0;         wRow = DM;   tabOff = RT1; }
    else if (bt < 7)  { src = emb2; M = NT2; rowBase = (bt-2)*64; wRow = 2*DM; tabOff = RT2; }
    else              { src = pe;   M = NTP; rowBase = (bt-7)*64; wRow = 3*DM; tabOff = RTP; }
    float* dst = (blockIdx.z ? g_rawB : g_rawA) + tabOff;

    const int kOff = blockIdx.z * 256;      // this block's K half

    const int tid = threadIdx.x;            // 0..127
    const int ty8 = (tid >> 4) * 8;         // row offset 0..56 (8 groups)
    const int tx4 = (tid & 15) * 4;         // col offset 0..60 (16 groups)
    const int colBase = blockIdx.y * 64;

    // A loader: 2 float4/thread/chunk. idx j*128+tid: row = idx>>2, k4 = (idx&3)*4
    const int lr0 = tid >> 2,      lk0 = (tid & 3) * 4;    // rows 0..31
    const int lr1 = 32 + (tid >> 2);                        // rows 32..63
    const bool aok0 = (rowBase + lr0 < M);
    const bool aok1 = (rowBase + lr1 < M);
    const float* aptr0 = src + (size_t)(rowBase + lr0) * DM + kOff + lk0;
    const float* aptr1 = src + (size_t)(rowBase + lr1) * DM + kOff + lk0;

    // B loader: 2 float4/thread/chunk. k = j*8 + (tid>>4), c4 = (tid&15)*4
    const int bk0 = tid >> 4;               // 0..7
    const int bk1 = 8 + bk0;                // 8..15
    const int bc4 = tx4;
    const float* wbase = W + (size_t)(wRow + kOff) * DM + colBase + bc4;

    unsigned long long acc[4][4];
    #pragma unroll
    for (int i = 0; i < 4; i++)
        #pragma unroll
        for (int c = 0; c < 4; c++) acc[i][c] = 0ull;

    float4 pa0, pa1, pb0, pb1;

    // prefetch chunk 0
    pa0 = aok0 ? *reinterpret_cast<const float4*>(aptr0) : make_float4(0.f,0.f,0.f,0.f);
    pa1 = aok1 ? *reinterpret_cast<const float4*>(aptr1) : make_float4(0.f,0.f,0.f,0.f);
    pb0 = *reinterpret_cast<const float4*>(wbase + (size_t)bk0 * DM);
    pb1 = *reinterpret_cast<const float4*>(wbase + (size_t)bk1 * DM);

    // store chunk 0
    As[0][lk0+0][lr0] = pa0.x; As[0][lk0+1][lr0] = pa0.y;
    As[0][lk0+2][lr0] = pa0.z; As[0][lk0+3][lr0] = pa0.w;
    As[0][lk0+0][lr1] = pa1.x; As[0][lk0+1][lr1] = pa1.y;
    As[0][lk0+2][lr1] = pa1.z; As[0][lk0+3][lr1] = pa1.w;
    Bs[0][bk0][bc4+0] = make_float2(pb0.x, pb0.x);
    Bs[0][bk0][bc4+1] = make_float2(pb0.y, pb0.y);
    Bs[0][bk0][bc4+2] = make_float2(pb0.z, pb0.z);
    Bs[0][bk0][bc4+3] = make_float2(pb0.w, pb0.w);
    Bs[0][bk1][bc4+0] = make_float2(pb1.x, pb1.x);
    Bs[0][bk1][bc4+1] = make_float2(pb1.y, pb1.y);
    Bs[0][bk1][bc4+2] = make_float2(pb1.z, pb1.z);
    Bs[0][bk1][bc4+3] = make_float2(pb1.w, pb1.w);
    __syncthreads();

    #pragma unroll 1
    for (int ch = 0; ch < 16; ch++) {
        const int buf = ch & 1;
        if (ch < 15) {
            const int k0 = (ch + 1) * 16;
            pa0 = aok0 ? *reinterpret_cast<const float4*>(aptr0 + k0) : make_float4(0.f,0.f,0.f,0.f);
            pa1 = aok1 ? *reinterpret_cast<const float4*>(aptr1 + k0) : make_float4(0.f,0.f,0.f,0.f);
            pb0 = *reinterpret_cast<const float4*>(wbase + (size_t)(k0 + bk0) * DM);
            pb1 = *reinterpret_cast<const float4*>(wbase + (size_t)(k0 + bk1) * DM);
        }

        #pragma unroll
        for (int kk = 0; kk < 16; kk++) {
            ulonglong2 aA  = *reinterpret_cast<const ulonglong2*>(&As[buf][kk][ty8]);
            ulonglong2 aB  = *reinterpret_cast<const ulonglong2*>(&As[buf][kk][ty8 + 4]);
            ulonglong2 b01 = *reinterpret_cast<const ulonglong2*>(&Bs[buf][kk][tx4]);
            ulonglong2 b23 = *reinterpret_cast<const ulonglong2*>(&Bs[buf][kk][tx4 + 2]);
            unsigned long long a2[4] = {aA.x, aA.y, aB.x, aB.y};
            #pragma unroll
            for (int i = 0; i < 4; i++) {
                fma2(acc[i][0], a2[i], b01.x);
                fma2(acc[i][1], a2[i], b01.y);
                fma2(acc[i][2], a2[i], b23.x);
                fma2(acc[i][3], a2[i], b23.y);
            }
        }

        if (ch < 15) {
            const int nb = buf ^ 1;
            As[nb][lk0+0][lr0] = pa0.x; As[nb][lk0+1][lr0] = pa0.y;
            As[nb][lk0+2][lr0] = pa0.z; As[nb][lk0+3][lr0] = pa0.w;
            As[nb][lk0+0][lr1] = pa1.x; As[nb][lk0+1][lr1] = pa1.y;
            As[nb][lk0+2][lr1] = pa1.z; As[nb][lk0+3][lr1] = pa1.w;
            Bs[nb][bk0][bc4+0] = make_float2(pb0.x, pb0.x);
            Bs[nb][bk0][bc4+1] = make_float2(pb0.y, pb0.y);
            Bs[nb][bk0][bc4+2] = make_float2(pb0.z, pb0.z);
            Bs[nb][bk0][bc4+3] = make_float2(pb0.w, pb0.w);
            Bs[nb][bk1][bc4+0] = make_float2(pb1.x, pb1.x);
            Bs[nb][bk1][bc4+1] = make_float2(pb1.y, pb1.y);
            Bs[nb][bk1][bc4+2] = make_float2(pb1.z, pb1.z);
            Bs[nb][bk1][bc4+3] = make_float2(pb1.w, pb1.w);
            __syncthreads();
        }
    }

    #pragma unroll
    for (int i = 0; i < 4; i++) {
        float2 u0 = unpack2(acc[i][0]);
        float2 u1 = unpack2(acc[i][1]);
        float2 u2 = unpack2(acc[i][2]);
        float2 u3 = unpack2(acc[i][3]);
        int re = rowBase + ty8 + 2*i;
        if (re < M) {
            float4 o = make_float4(u0.x, u1.x, u2.x, u3.x);
            *reinterpret_cast<float4*>(dst + (size_t)re * DM + colBase + tx4) = o;
        }
        if (re + 1 < M) {
            float4 o = make_float4(u0.y, u1.y, u2.y, u3.y);
            *reinterpret_cast<float4*>(dst + (size_t)(re + 1) * DM + colBase + tx4) = o;
        }
    }
}

// ---------------------------------------------------------------------------
// Kernel 2: reduce K-halves + fuse T01 = T0[i]+T1[j] + add bias to Tp.
// grid = 168 + 288 + 2048 = 2504 rows, 128 threads (float4 each).
// ---------------------------------------------------------------------------
__global__ void reduce_kernel(const float* __restrict__ bias) {
    const int r = blockIdx.x;
    const int c = 4 * threadIdx.x;

    float4 o;
    float* dst;
    if (r < 168) {
        const int i = r / 24, j = r % 24;
        float4 a0 = *reinterpret_cast<const float4*>(g_rawA + RT0 + (size_t)i * DM + c);
        float4 b0 = *reinterpret_cast<const float4*>(g_rawB + RT0 + (size_t)i * DM + c);
        float4 a1 = *reinterpret_cast<const float4*>(g_rawA + RT1 + (size_t)j * DM + c);
        float4 b1 = *reinterpret_cast<const float4*>(g_rawB + RT1 + (size_t)j * DM + c);
        o = make_float4(a0.x + b0.x + a1.x + b1.x,
                        a0.y + b0.y + a1.y + b1.y,
                        a0.z + b0.z + a1.z + b1.z,
                        a0.w + b0.w + a1.w + b1.w);
        dst = g_tab + OT01 + (size_t)r * DM + c;
    } else if (r < 168 + NT2) {
        const int rr = r - 168;
        float4 a = *reinterpret_cast<const float4*>(g_rawA + RT2 + (size_t)rr * DM + c);
        float4 b = *reinterpret_cast<const float4*>(g_rawB + RT2 + (size_t)rr * DM + c);
        o = make_float4(a.x + b.x, a.y + b.y, a.z + b.z, a.w + b.w);
        dst = g_tab + OT2 + (size_t)rr * DM + c;
    } else {
        const int rr = r - 168 - NT2;
        float4 a = *reinterpret_cast<const float4*>(g_rawA + RTP + (size_t)rr * DM + c);
        float4 b = *reinterpret_cast<const float4*>(g_rawB + RTP + (size_t)rr * DM + c);
        float4 bb = *reinterpret_cast<const float4*>(bias + c);
        o = make_float4(a.x + b.x + bb.x, a.y + b.y + bb.y,
                        a.z + b.z + bb.z, a.w + b.w + bb.w);
        dst = g_tab + OTP + (size_t)rr * DM + c;
    }
    *reinterpret_cast<float4*>(dst) = o;
}

// ---------------------------------------------------------------------------
// Kernel 3: gather-add. 256 threads = 2 positions/block, grid 1024.
// out[token] = T01[i0*24+i1] + T2[i2] + Tp[l]
// ---------------------------------------------------------------------------
__global__ void gather_kernel(const int* __restrict__ in0, const int* __restrict__ tg0,
                              const int* __restrict__ in1, const int* __restrict__ tg1,
                              const int* __restrict__ in2, const int* __restrict__ tg2,
                              float* __restrict__ out) {
    const int t = threadIdx.x;
    const int half = t >> 7;           // which position
    const int lane = t & 127;          // column group
    const int l = blockIdx.x * 2 + half;

    __shared__ int s01[2][64], s2[2][64];
    if (lane < 64) {
        int s = lane >> 5, b = lane & 31;
        int off = b * PP + l;
        int i0 = (s ? tg0 : in0)[off];
        int i1 = (s ? tg1 : in1)[off];
        int i2 = (s ? tg2 : in2)[off];
        s01[half][lane] = i0 * 24 + i1;
        s2[half][lane]  = i2;
    }

    const float4 tp = *reinterpret_cast<const float4*>(g_tab + OTP + (size_t)l * DM + 4 * lane);

    __syncthreads();

    float4* outv = reinterpret_cast<float4*>(out);

    #pragma unroll 4
    for (int p = 0; p < 64; p++) {
        const float4 v01 = *reinterpret_cast<const float4*>(g_tab + OT01 + (size_t)s01[half][p] * DM + 4 * lane);
        const float4 v2  = *reinterpret_cast<const float4*>(g_tab + OT2  + (size_t)s2[half][p]  * DM + 4 * lane);
        float4 o;
        o.x = v01.x + v2.x + tp.x;
        o.y = v01.y + v2.y + tp.y;
        o.z = v01.z + v2.z + tp.z;
        o.w = v01.w + v2.w + tp.w;
        outv[((size_t)p * PP + l) * (DM / 4) + lane] = o;
    }
}

extern "C" void kernel_launch(void* const* d_in, const int* in_sizes, int n_in,
                              void* d_out, int out_size) {
    const int*   in0  = (const int*)d_in[0];
    const int*   tg0  = (const int*)d_in[1];
    const int*   in1  = (const int*)d_in[2];
    const int*   tg1  = (const int*)d_in[3];
    const int*   in2  = (const int*)d_in[4];
    const int*   tg2  = (const int*)d_in[5];
    const float* emb0 = (const float*)d_in[6];
    const float* emb1 = (const float*)d_in[7];
    const float* emb2 = (const float*)d_in[8];
    const float* pe   = (const float*)d_in[9];
    const float* W    = (const float*)d_in[10];
    const float* bias = (const float*)d_in[11];
    float* out = (float*)d_out;

    dim3 ggrid(39, 8, 2);
    table_gemm_kernel<<<ggrid, 128>>>(emb0, emb1, emb2, pe, W);
    reduce_kernel<<<2504, 128>>>(bias);
    gather_kernel<<<1024, 256>>>(in0, tg0, in1, tg1, in2, tg2, out);
}